// round 8
// baseline (speedup 1.0000x reference)
#include <cuda_runtime.h>
#include <cstdint>
#include <cstddef>

// E3Hamiltonian: block-diagonal per-edge transform, ROW=282 floats per edge.
// out[n, off + p*m + j] = sum_mm cg[j*m+mm] * in[n, off + p*m + mm]
// Types: ss(off0,np6,m1) sp(off6,np9,m3) sd(off33,np6,m5)
//        pp(off63,np6,m9) pd(off117,np6,m15) dd(off207,np3,m25)

#define ROW 282
#define TILE 32                        // 600000 % 32 == 0
#define THREADS 512                    // 16 warps
#define NIN 3
#define NOUT 2
#define TILE_FLOATS (TILE * ROW)       // 9024
#define TILE_BYTES  (TILE_FLOATS * 4)  // 36096
#define SMEM_TOTAL ((NIN + NOUT) * TILE_BYTES + 32)   // 180512 -> 1 CTA/SM
#define CGR 75                         // max cg registers per thread

// ---------------- PTX helpers ----------------
__device__ __forceinline__ uint32_t smem_u32(const void* p) {
    return (uint32_t)__cvta_generic_to_shared(p);
}
__device__ __forceinline__ void mbar_init(uint32_t mbar, uint32_t count) {
    asm volatile("mbarrier.init.shared.b64 [%0], %1;" :: "r"(mbar), "r"(count) : "memory");
}
__device__ __forceinline__ void mbar_expect_tx(uint32_t mbar, uint32_t bytes) {
    asm volatile("mbarrier.arrive.expect_tx.shared::cta.b64 _, [%0], %1;"
                 :: "r"(mbar), "r"(bytes) : "memory");
}
__device__ __forceinline__ void mbar_wait(uint32_t mbar, uint32_t parity) {
    asm volatile(
        "{\n\t.reg .pred P;\n\t"
        "WL_%=:\n\t"
        "mbarrier.try_wait.parity.acquire.cta.shared::cta.b64 P, [%0], %1, 0x989680;\n\t"
        "@P bra.uni WD_%=;\n\t"
        "bra.uni WL_%=;\n\t"
        "WD_%=:\n\t}"
        :: "r"(mbar), "r"(parity) : "memory");
}
__device__ __forceinline__ void tma_load_1d(uint32_t dst_smem, const void* src_gmem,
                                            uint32_t bytes, uint32_t mbar) {
    asm volatile(
        "cp.async.bulk.shared::cta.global.mbarrier::complete_tx::bytes [%0], [%1], %2, [%3];"
        :: "r"(dst_smem), "l"(src_gmem), "r"(bytes), "r"(mbar) : "memory");
}
__device__ __forceinline__ void tma_store_1d(void* dst_gmem, uint32_t src_smem, uint32_t bytes) {
    asm volatile(
        "cp.async.bulk.global.shared::cta.bulk_group [%0], [%1], %2;"
        :: "l"(dst_gmem), "r"(src_smem), "r"(bytes) : "memory");
}
__device__ __forceinline__ void tma_commit() {
    asm volatile("cp.async.bulk.commit_group;" ::: "memory");
}
__device__ __forceinline__ void tma_wait_group_1() {
    asm volatile("cp.async.bulk.wait_group 1;" ::: "memory");
}
__device__ __forceinline__ void tma_wait_all() {
    asm volatile("cp.async.bulk.wait_group 0;" ::: "memory");
}
__device__ __forceinline__ void fence_async_shared() {
    asm volatile("fence.proxy.async.shared::cta;" ::: "memory");
}

// ---------------- cg register load / compute ----------------
// load NR rows (each M floats) of cg starting at row J0 into cgr[CB..]
template <int M, int NR, int J0, int CB>
__device__ __forceinline__ void loadcg(float (&cgr)[CGR], const float* __restrict__ g) {
#pragma unroll
    for (int rr = 0; rr < NR; rr++)
#pragma unroll
        for (int mm = 0; mm < M; mm++)
            cgr[CB + rr * M + mm] = g[(J0 + rr) * M + mm];
}

// compute NR output rows (j = J0..J0+NR) for all NP pairs of a type at OFF.
// inputs: smem in-row; cg: registers; outputs: smem out-row. 2 acc chains/row.
template <int M, int NR, int NP, int OFF, int J0, int CB>
__device__ __forceinline__ void comp(const float (&cgr)[CGR],
                                     const float* __restrict__ ib,
                                     float* __restrict__ ob) {
#pragma unroll
    for (int p = 0; p < NP; p++) {
        float x[M];
#pragma unroll
        for (int mm = 0; mm < M; mm++) x[mm] = ib[OFF + p * M + mm];
#pragma unroll
        for (int rr = 0; rr < NR; rr++) {
            float a0 = 0.f, a1 = 0.f;
#pragma unroll
            for (int mm = 0; mm < M; mm += 2) {
                a0 += cgr[CB + rr * M + mm] * x[mm];
                if (mm + 1 < M) a1 += cgr[CB + rr * M + mm + 1] * x[mm + 1];
            }
            ob[OFF + p * M + J0 + rr] = a0 + a1;
        }
    }
}

// 16-warp schedule (cg regs <= 75, warp-FFMA 225-282 per tile):
// w0..w7 : dd rows {3w,3w+1,3w+2}
// w8     : dd row 24 + pd rows 0,1 + sp row 0
// w9..w12: pd rows {2,3,4},{5,6,7},{8,9,10},{11,12,13}
// w13    : pd row 14 + pp rows 0,1,2 + sp row 1
// w14    : pp rows 3,4,5 + sd rows 0,1,2 + sp row 2
// w15    : pp rows 6,7,8 + sd rows 3,4 + ss row 0
__device__ __forceinline__ void load_cg_regs(float (&c)[CGR], int w,
        const float* ss, const float* sp, const float* sd,
        const float* pp, const float* pd, const float* dd) {
    switch (w) {
        case 0:  loadcg<25,3,0,0>(c, dd); break;
        case 1:  loadcg<25,3,3,0>(c, dd); break;
        case 2:  loadcg<25,3,6,0>(c, dd); break;
        case 3:  loadcg<25,3,9,0>(c, dd); break;
        case 4:  loadcg<25,3,12,0>(c, dd); break;
        case 5:  loadcg<25,3,15,0>(c, dd); break;
        case 6:  loadcg<25,3,18,0>(c, dd); break;
        case 7:  loadcg<25,3,21,0>(c, dd); break;
        case 8:  loadcg<25,1,24,0>(c, dd); loadcg<15,2,0,25>(c, pd); loadcg<3,1,0,55>(c, sp); break;
        case 9:  loadcg<15,3,2,0>(c, pd); break;
        case 10: loadcg<15,3,5,0>(c, pd); break;
        case 11: loadcg<15,3,8,0>(c, pd); break;
        case 12: loadcg<15,3,11,0>(c, pd); break;
        case 13: loadcg<15,1,14,0>(c, pd); loadcg<9,3,0,15>(c, pp); loadcg<3,1,1,42>(c, sp); break;
        case 14: loadcg<9,3,3,0>(c, pp); loadcg<5,3,0,27>(c, sd); loadcg<3,1,2,42>(c, sp); break;
        default: loadcg<9,3,6,0>(c, pp); loadcg<5,2,3,27>(c, sd); loadcg<1,1,0,37>(c, ss); break;
    }
}

__device__ __forceinline__ void compute_warp(const float (&c)[CGR], int w,
        const float* __restrict__ ib, float* __restrict__ ob) {
    switch (w) {
        case 0:  comp<25,3,3,207,0,0>(c, ib, ob); break;
        case 1:  comp<25,3,3,207,3,0>(c, ib, ob); break;
        case 2:  comp<25,3,3,207,6,0>(c, ib, ob); break;
        case 3:  comp<25,3,3,207,9,0>(c, ib, ob); break;
        case 4:  comp<25,3,3,207,12,0>(c, ib, ob); break;
        case 5:  comp<25,3,3,207,15,0>(c, ib, ob); break;
        case 6:  comp<25,3,3,207,18,0>(c, ib, ob); break;
        case 7:  comp<25,3,3,207,21,0>(c, ib, ob); break;
        case 8:  comp<25,1,3,207,24,0>(c, ib, ob); comp<15,2,6,117,0,25>(c, ib, ob);
                 comp<3,1,9,6,0,55>(c, ib, ob); break;
        case 9:  comp<15,3,6,117,2,0>(c, ib, ob); break;
        case 10: comp<15,3,6,117,5,0>(c, ib, ob); break;
        case 11: comp<15,3,6,117,8,0>(c, ib, ob); break;
        case 12: comp<15,3,6,117,11,0>(c, ib, ob); break;
        case 13: comp<15,1,6,117,14,0>(c, ib, ob); comp<9,3,6,63,0,15>(c, ib, ob);
                 comp<3,1,9,6,1,42>(c, ib, ob); break;
        case 14: comp<9,3,6,63,3,0>(c, ib, ob); comp<5,3,6,33,0,27>(c, ib, ob);
                 comp<3,1,9,6,2,42>(c, ib, ob); break;
        default: comp<9,3,6,63,6,0>(c, ib, ob); comp<5,2,6,33,3,27>(c, ib, ob);
                 comp<1,1,6,0,0,37>(c, ib, ob); break;
    }
}

extern __shared__ __align__(128) unsigned char dynsmem[];

__global__ __launch_bounds__(THREADS, 1)
void e3h_kernel(const float* __restrict__ ef,
                const float* __restrict__ cg_ss, const float* __restrict__ cg_sp,
                const float* __restrict__ cg_sd, const float* __restrict__ cg_pp,
                const float* __restrict__ cg_pd, const float* __restrict__ cg_dd,
                float* __restrict__ out, int n, int ntiles) {
    float* ibuf = reinterpret_cast<float*>(dynsmem);           // 3 in tiles
    float* obuf = ibuf + NIN * TILE_FLOATS;                    // 2 out tiles
    unsigned long long* mb = reinterpret_cast<unsigned long long*>(obuf + NOUT * TILE_FLOATS);

    const int tid = threadIdx.x;
    const int lane = tid & 31;
    const int warp = tid >> 5;

    uint32_t full_b[NIN], in_a[NIN], out_a[NOUT];
#pragma unroll
    for (int b = 0; b < NIN; b++) {
        full_b[b] = smem_u32(mb + b);
        in_a[b]   = smem_u32(ibuf + b * TILE_FLOATS);
    }
#pragma unroll
    for (int b = 0; b < NOUT; b++) out_a[b] = smem_u32(obuf + b * TILE_FLOATS);

    if (tid == 0) {
#pragma unroll
        for (int b = 0; b < NIN; b++) mbar_init(full_b[b], 1);
    }

    // ---- cg -> registers, once per kernel ----
    float cgr[CGR];
    load_cg_regs(cgr, warp, cg_ss, cg_sp, cg_sd, cg_pp, cg_pd, cg_dd);
    __syncthreads();   // mbar init visible

    const int bid = blockIdx.x;
    const int grid = gridDim.x;
    const int cnt = (bid < ntiles) ? (ntiles - bid + grid - 1) / grid : 0;

    // prologue: loads for tiles 0,1
    if (tid == 0) {
        const int npro = (cnt < 2) ? cnt : 2;
        for (int p = 0; p < npro; p++) {
            mbar_expect_tx(full_b[p], TILE_BYTES);
            tma_load_1d(in_a[p], ef + ((size_t)bid + (size_t)p * grid) * TILE_FLOATS,
                        TILE_BYTES, full_b[p]);
        }
    }

    for (int k = 0; k < cnt; k++) {
        const int ib = k % NIN, ob = k & 1;
        const size_t tile = (size_t)bid + (size_t)k * grid;

        if (tid == 0) {
            if (k >= 2) tma_wait_group_1();   // store k-2 (obuf ob) drained
            if (k + 2 < cnt) {                // inbuf (k+2)%3 == (k-1)%3: free
                const int nb = (k + 2) % NIN;
                mbar_expect_tx(full_b[nb], TILE_BYTES);
                tma_load_1d(in_a[nb], ef + (tile + 2 * (size_t)grid) * TILE_FLOATS,
                            TILE_BYTES, full_b[nb]);
            }
        }
        __syncthreads();                       // obuf[ob] reusable for everyone
        mbar_wait(full_b[ib], (k / NIN) & 1);  // tile k data in smem

        compute_warp(cgr, warp,
                     ibuf + ib * TILE_FLOATS + lane * ROW,
                     obuf + ob * TILE_FLOATS + lane * ROW);
        __syncthreads();

        if (tid == 0) {
            fence_async_shared();
            tma_store_1d(out + tile * TILE_FLOATS, out_a[ob], TILE_BYTES);
            tma_commit();
        }
    }

    // ---- remainder edges (600000 % 32 == 0; generic fallback) ----
    const int rem = n - ntiles * TILE;
    if (rem > 0 && bid == 0) {
        if (tid == 0) tma_wait_all();
        __syncthreads();
        const size_t base = (size_t)ntiles * TILE_FLOATS;
        const int cntf = rem * ROW;
        for (int i = tid; i < cntf; i += THREADS) ibuf[i] = ef[base + i];
        __syncthreads();
        if (lane < rem)
            compute_warp(cgr, warp, ibuf + lane * ROW, obuf + lane * ROW);
        __syncthreads();
        for (int i = tid; i < cntf; i += THREADS) out[base + i] = obuf[i];
    }

    if (tid == 0) tma_wait_all();   // drain bulk stores before exit
}

extern "C" void kernel_launch(void* const* d_in, const int* in_sizes, int n_in,
                              void* d_out, int out_size) {
    const float* ef    = (const float*)d_in[0];
    const float* cg_ss = (const float*)d_in[1];
    const float* cg_sp = (const float*)d_in[2];
    const float* cg_sd = (const float*)d_in[3];
    const float* cg_pp = (const float*)d_in[4];
    const float* cg_pd = (const float*)d_in[5];
    const float* cg_dd = (const float*)d_in[6];
    float* out = (float*)d_out;

    int n = in_sizes[0] / ROW;
    int ntiles = n / TILE;

    int sms = 148;
    cudaDeviceGetAttribute(&sms, cudaDevAttrMultiProcessorCount, 0);
    int grid = sms;                         // 1 CTA/SM (180KB smem)
    if (ntiles > 0 && grid > ntiles) grid = ntiles;
    if (grid < 1) grid = 1;

    cudaFuncSetAttribute(e3h_kernel, cudaFuncAttributeMaxDynamicSharedMemorySize, SMEM_TOTAL);
    e3h_kernel<<<grid, THREADS, SMEM_TOTAL>>>(ef, cg_ss, cg_sp, cg_sd, cg_pp, cg_pd, cg_dd,
                                              out, n, ntiles);
}

// round 9
// speedup vs baseline: 1.9594x; 1.9594x over previous
#include <cuda_runtime.h>
#include <cstdint>
#include <cstddef>

// E3Hamiltonian: block-diagonal per-edge transform, ROW=282 floats per edge.
// out[n, off + p*m + j] = sum_mm cg[j*m+mm] * in[n, off + p*m + mm]
// Blocks: ss(off0,np6,m1) sp(off6,np9,m3) sd(off33,np6,m5)
//         pp(off63,np6,m9) pd(off117,np6,m15) dd(off207,np3,m25)

#define ROW 282
#define TILE 30                           // 600000 % 30 == 0 -> 20000 tiles
#define THREADS 256
#define TILE_FLOATS (TILE * ROW)          // 8460
#define TILE_BYTES  (TILE_FLOATS * 4)     // 33840 (16B multiple)
#define CG_TOTAL 1104
#define SMEM_TOTAL (2 * TILE_BYTES + CG_TOTAL * 4 + 16)  // 72112 B -> 3 CTAs/SM

// ---------------- PTX helpers ----------------
__device__ __forceinline__ uint32_t smem_u32(const void* p) {
    return (uint32_t)__cvta_generic_to_shared(p);
}
__device__ __forceinline__ void mbar_init(uint32_t mbar, uint32_t count) {
    asm volatile("mbarrier.init.shared.b64 [%0], %1;" :: "r"(mbar), "r"(count) : "memory");
}
__device__ __forceinline__ void mbar_expect_tx(uint32_t mbar, uint32_t bytes) {
    asm volatile("mbarrier.arrive.expect_tx.shared::cta.b64 _, [%0], %1;"
                 :: "r"(mbar), "r"(bytes) : "memory");
}
__device__ __forceinline__ void mbar_wait(uint32_t mbar, uint32_t parity) {
    asm volatile(
        "{\n\t.reg .pred P;\n\t"
        "WL_%=:\n\t"
        "mbarrier.try_wait.parity.acquire.cta.shared::cta.b64 P, [%0], %1, 0x989680;\n\t"
        "@P bra.uni WD_%=;\n\t"
        "bra.uni WL_%=;\n\t"
        "WD_%=:\n\t}"
        :: "r"(mbar), "r"(parity) : "memory");
}
__device__ __forceinline__ void tma_load_1d(uint32_t dst_smem, const void* src_gmem,
                                            uint32_t bytes, uint32_t mbar) {
    asm volatile(
        "cp.async.bulk.shared::cta.global.mbarrier::complete_tx::bytes [%0], [%1], %2, [%3];"
        :: "r"(dst_smem), "l"(src_gmem), "r"(bytes), "r"(mbar) : "memory");
}
__device__ __forceinline__ void tma_store_1d(void* dst_gmem, uint32_t src_smem, uint32_t bytes) {
    asm volatile(
        "cp.async.bulk.global.shared::cta.bulk_group [%0], [%1], %2;"
        :: "l"(dst_gmem), "r"(src_smem), "r"(bytes) : "memory");
}
__device__ __forceinline__ void tma_commit() {
    asm volatile("cp.async.bulk.commit_group;" ::: "memory");
}
__device__ __forceinline__ void tma_wait_all() {
    asm volatile("cp.async.bulk.wait_group 0;" ::: "memory");
}
__device__ __forceinline__ void fence_async_shared() {
    asm volatile("fence.proxy.async.shared::cta;" ::: "memory");
}

// ---------------- compute (R1/R2-proven, 64 regs) ----------------
// One m x m matvec, in place on this lane's row. cg rows padded to MP (16B).
template <int M, int MP>
__device__ __forceinline__ void task(float* __restrict__ r,
                                     const float* __restrict__ cg, int col) {
    float in[M];
#pragma unroll
    for (int mm = 0; mm < M; mm++) in[mm] = r[col + mm];
#pragma unroll
    for (int j = 0; j < M; j++) {
        const float4* c4 = reinterpret_cast<const float4*>(cg + j * MP);
        float acc = 0.f;
#pragma unroll
        for (int k = 0; k < MP / 4; k++) {
            float4 c = c4[k];
            if (4 * k + 0 < M) acc += c.x * in[4 * k + 0];
            if (4 * k + 1 < M) acc += c.y * in[4 * k + 1];
            if (4 * k + 2 < M) acc += c.z * in[4 * k + 2];
            if (4 * k + 3 < M) acc += c.w * in[4 * k + 3];
        }
        r[col + j] = acc;
    }
}

// warp-partitioned task dispatch; warps own disjoint column ranges, lane = edge.
__device__ __forceinline__ void compute_row(float* __restrict__ r,
                                            const float* __restrict__ s_cg, int warp) {
    switch (warp) {
        case 0: task<25, 28>(r, s_cg + 404, 207); break;
        case 1: task<25, 28>(r, s_cg + 404, 232); break;
        case 2: task<25, 28>(r, s_cg + 404, 257); break;
        case 3: task<15, 16>(r, s_cg + 164, 117);
                task<15, 16>(r, s_cg + 164, 132); break;
        case 4: task<15, 16>(r, s_cg + 164, 147);
                task<15, 16>(r, s_cg + 164, 162); break;
        case 5: task<15, 16>(r, s_cg + 164, 177);
                task<15, 16>(r, s_cg + 164, 192); break;
        case 6: {
#pragma unroll
            for (int p = 0; p < 5; p++) task<9, 12>(r, s_cg + 56, 63 + 9 * p);
            break;
        }
        default: {  // warp 7
            task<9, 12>(r, s_cg + 56, 108);
#pragma unroll
            for (int p = 0; p < 6; p++) task<5, 8>(r, s_cg + 16, 33 + 5 * p);
#pragma unroll
            for (int p = 0; p < 9; p++) task<3, 4>(r, s_cg + 4, 6 + 3 * p);
#pragma unroll
            for (int p = 0; p < 6; p++) task<1, 4>(r, s_cg + 0, p);
            break;
        }
    }
}

__device__ __forceinline__ void fill_cg(float* __restrict__ dst, const float* __restrict__ src,
                                        int m, int mp, int tid) {
    int total = m * mp;
    for (int i = tid; i < total; i += THREADS) {
        int row = i / mp, c = i - row * mp;
        dst[i] = (c < m) ? src[row * m + c] : 0.f;
    }
}

extern __shared__ __align__(128) unsigned char dynsmem[];

__global__ __launch_bounds__(THREADS, 3)
void e3h_kernel(const float* __restrict__ ef,
                const float* __restrict__ cg_ss, const float* __restrict__ cg_sp,
                const float* __restrict__ cg_sd, const float* __restrict__ cg_pp,
                const float* __restrict__ cg_pd, const float* __restrict__ cg_dd,
                float* __restrict__ out, int n, int ntiles) {
    float* buf0 = reinterpret_cast<float*>(dynsmem);
    float* buf1 = buf0 + TILE_FLOATS;
    float* s_cg = buf1 + TILE_FLOATS;
    unsigned long long* mb = reinterpret_cast<unsigned long long*>(s_cg + CG_TOTAL);

    const int tid = threadIdx.x;
    const int lane = tid & 31;
    const int warp = tid >> 5;

    fill_cg(s_cg + 0,   cg_ss, 1, 4,  tid);
    fill_cg(s_cg + 4,   cg_sp, 3, 4,  tid);
    fill_cg(s_cg + 16,  cg_sd, 5, 8,  tid);
    fill_cg(s_cg + 56,  cg_pp, 9, 12, tid);
    fill_cg(s_cg + 164, cg_pd, 15, 16, tid);
    fill_cg(s_cg + 404, cg_dd, 25, 28, tid);

    const uint32_t mbad0 = smem_u32(mb);
    const uint32_t mbad1 = smem_u32(mb + 1);
    const uint32_t sb0 = smem_u32(buf0);
    const uint32_t sb1 = smem_u32(buf1);
    if (tid == 0) { mbar_init(mbad0, 1); mbar_init(mbad1, 1); }
    __syncthreads();

    const int bid = blockIdx.x;
    const int grid = gridDim.x;
    const int cnt = (bid < ntiles) ? (ntiles - bid + grid - 1) / grid : 0;

    if (cnt > 0 && tid == 0) {
        mbar_expect_tx(mbad0, TILE_BYTES);
        tma_load_1d(sb0, ef + (size_t)bid * TILE_FLOATS, TILE_BYTES, mbad0);
    }

    for (int k = 0; k < cnt; k++) {
        const size_t tile = (size_t)bid + (size_t)k * grid;
        if (tid == 0 && k + 1 < cnt) {
            // buffer (k+1)&1 was last read by store of tile k-1 -> drain stores first
            tma_wait_all();
            const uint32_t mbn = ((k + 1) & 1) ? mbad1 : mbad0;
            const uint32_t sbn = ((k + 1) & 1) ? sb1 : sb0;
            mbar_expect_tx(mbn, TILE_BYTES);
            tma_load_1d(sbn, ef + (tile + grid) * TILE_FLOATS, TILE_BYTES, mbn);
        }
        mbar_wait((k & 1) ? mbad1 : mbad0, (k >> 1) & 1);

        float* s = (k & 1) ? buf1 : buf0;
        if (lane < TILE) compute_row(s + lane * ROW, s_cg, warp);
        __syncthreads();

        if (tid == 0) {
            fence_async_shared();
            tma_store_1d(out + tile * TILE_FLOATS, (k & 1) ? sb1 : sb0, TILE_BYTES);
            tma_commit();
        }
    }

    // ---- remainder edges (600000 % 30 == 0; kept for generality) ----
    const int rem = n - ntiles * TILE;
    if (rem > 0 && bid == 0) {
        if (tid == 0) tma_wait_all();
        __syncthreads();
        const size_t base = (size_t)ntiles * TILE_FLOATS;
        const int cntf = rem * ROW;
        for (int i = tid; i < cntf; i += THREADS) buf0[i] = ef[base + i];
        __syncthreads();
        if (lane < rem) compute_row(buf0 + lane * ROW, s_cg, warp);
        __syncthreads();
        for (int i = tid; i < cntf; i += THREADS) out[base + i] = buf0[i];
    }

    if (tid == 0) tma_wait_all();   // ensure bulk stores complete before exit
}

extern "C" void kernel_launch(void* const* d_in, const int* in_sizes, int n_in,
                              void* d_out, int out_size) {
    const float* ef    = (const float*)d_in[0];
    const float* cg_ss = (const float*)d_in[1];
    const float* cg_sp = (const float*)d_in[2];
    const float* cg_sd = (const float*)d_in[3];
    const float* cg_pp = (const float*)d_in[4];
    const float* cg_pd = (const float*)d_in[5];
    const float* cg_dd = (const float*)d_in[6];
    float* out = (float*)d_out;

    int n = in_sizes[0] / ROW;
    int ntiles = n / TILE;

    int sms = 148;
    cudaDeviceGetAttribute(&sms, cudaDevAttrMultiProcessorCount, 0);
    int grid = 3 * sms;                     // 3 CTAs/SM
    if (ntiles > 0 && grid > ntiles) grid = ntiles;
    if (grid < 1) grid = 1;

    cudaFuncSetAttribute(e3h_kernel, cudaFuncAttributeMaxDynamicSharedMemorySize, SMEM_TOTAL);
    e3h_kernel<<<grid, THREADS, SMEM_TOTAL>>>(ef, cg_ss, cg_sp, cg_sd, cg_pp, cg_pd, cg_dd,
                                              out, n, ntiles);
}